// round 15
// baseline (speedup 1.0000x reference)
#include <cuda_runtime.h>
#include <cuda_bf16.h>
#include <math.h>
#include <stdint.h>

#define HW 128
#define C_MID 64
#define MAXB 8

// ---------------- scratch (no allocs allowed) ----------------
__device__ float g_hm [MAXB * HW * HW];
__device__ float g_hmf[MAXB * HW * HW];
// main weight fragments, mma-B register layout:
// [tap(9)][npair(4)][kc(4)][hl(2)][lane(32)][reg(4)] uint32
__device__ __align__(16) uint32_t g_wfrag[9 * 4 * 4 * 2 * 32 * 4];
// extra-channel fragments: [npair(4)][kc(2)][hl(2)][lane(32)][reg(4)]
__device__ __align__(16) uint32_t g_efrag[4 * 2 * 2 * 32 * 4];
__device__ int g_coor64;

// ---------------- helpers ----------------
__device__ __forceinline__ uint32_t smem_u32(const void* p) {
    uint32_t a;
    asm("{ .reg .u64 t; cvta.to.shared.u64 t, %1; cvt.u32.u64 %0, t; }" : "=r"(a) : "l"(p));
    return a;
}
__device__ __forceinline__ void ldsm_x4(uint32_t addr, uint32_t& r0, uint32_t& r1,
                                        uint32_t& r2, uint32_t& r3) {
    asm volatile("ldmatrix.sync.aligned.m8n8.x4.shared.b16 {%0,%1,%2,%3}, [%4];"
                 : "=r"(r0), "=r"(r1), "=r"(r2), "=r"(r3) : "r"(addr));
}
__device__ __forceinline__ void mma_bf16(float* d, const uint32_t* a,
                                         uint32_t b0, uint32_t b1) {
    asm volatile(
        "mma.sync.aligned.m16n8k16.row.col.f32.bf16.bf16.f32 "
        "{%0,%1,%2,%3},{%4,%5,%6,%7},{%8,%9},{%0,%1,%2,%3};"
        : "+f"(d[0]), "+f"(d[1]), "+f"(d[2]), "+f"(d[3])
        : "r"(a[0]), "r"(a[1]), "r"(a[2]), "r"(a[3]), "r"(b0), "r"(b1));
}
__device__ __forceinline__ uint32_t pack_hl(float v0, float v1, uint32_t& lo) {
    __nv_bfloat16 h0 = __float2bfloat16(v0);
    __nv_bfloat16 h1 = __float2bfloat16(v1);
    __nv_bfloat16 l0 = __float2bfloat16(v0 - __bfloat162float(h0));
    __nv_bfloat16 l1 = __float2bfloat16(v1 - __bfloat162float(h1));
    lo = (uint32_t)__bfloat16_as_ushort(l0) | ((uint32_t)__bfloat16_as_ushort(l1) << 16);
    return (uint32_t)__bfloat16_as_ushort(h0) | ((uint32_t)__bfloat16_as_ushort(h1) << 16);
}
__device__ __forceinline__ uint32_t pack_sel(float v0, float v1, int hl) {
    uint32_t lo, hi = pack_hl(v0, v1, lo);
    return hl ? lo : hi;
}

// extra-channel folded weight value: esum[o][slot]
__device__ __forceinline__ float esum_val(const float* __restrict__ comp_w,
                                          const float* __restrict__ att_w,
                                          const float* __restrict__ att_b,
                                          int o, int slot) {
    if (slot >= 27) return 0.f;
    int tap = slot / 3, j = slot - 3 * tap;
    float s = 0.f;
    #pragma unroll 4
    for (int c = 0; c < 64; c++) {
        float w = comp_w[(o * 128 + 64 + c) * 9 + tap];
        float a = (j == 0) ? att_w[2 * c] : (j == 1) ? att_w[2 * c + 1] : att_b[c];
        s += w * a;
    }
    return s;
}

// ---------------- k1: setup (init heatmaps + detect + all weight fragments) ----------------
__global__ void setup_kernel(const int* __restrict__ rc_as_i32,
                             const float* __restrict__ comp_w,
                             const float* __restrict__ att_w,
                             const float* __restrict__ att_b,
                             int nz, int init_blocks) {
    if ((int)blockIdx.x < init_blocks) {
        int i = blockIdx.x * blockDim.x + threadIdx.x;
        if (i < nz) { g_hm[i] = 0.0f; g_hmf[i] = 0.0f; }
        return;
    }
    int t = (blockIdx.x - init_blocks) * blockDim.x + threadIdx.x;
    if (t == 0) {
        int all0 = 1;
        #pragma unroll 1
        for (int i = 1; i < 128; i += 2) all0 &= (rc_as_i32[i] == 0);
        g_coor64 = all0;
    }
    if (t < 9216) {               // main: [tap][npair][kc][hl][lane]
        int lane = t & 31;
        int r = t >> 5;
        int hl = r & 1;
        int kc = (r >> 1) & 3;
        int npair = (r >> 3) & 3;
        int tap = r >> 5;
        uint32_t v[4];
        #pragma unroll
        for (int m = 0; m < 4; m++) {
            int nb = 2 * npair + (m >> 1);
            int oc = nb * 8 + (lane >> 2);
            int k0 = kc * 16 + (m & 1) * 8 + 2 * (lane & 3);
            float w0 = comp_w[(oc * 128 + k0) * 9 + tap];
            float w1 = comp_w[(oc * 128 + k0 + 1) * 9 + tap];
            v[m] = pack_sel(w0, w1, hl);
        }
        *(uint4*)&g_wfrag[t * 4] = make_uint4(v[0], v[1], v[2], v[3]);
    } else if (t < 9216 + 512) {  // extra: [npair][kc][hl][lane], esum inline
        int e = t - 9216;
        int lane = e & 31;
        int r = e >> 5;
        int hl = r & 1;
        int kc = (r >> 1) & 1;
        int npair = r >> 2;
        uint32_t v[4];
        #pragma unroll
        for (int m = 0; m < 4; m++) {
            int nb = 2 * npair + (m >> 1);
            int oc = nb * 8 + (lane >> 2);
            int s0 = kc * 16 + (m & 1) * 8 + 2 * (lane & 3);
            float w0 = esum_val(comp_w, att_w, att_b, oc, s0);
            float w1 = esum_val(comp_w, att_w, att_b, oc, s0 + 1);
            v[m] = pack_sel(w0, w1, hl);
        }
        *(uint4*)&g_efrag[e * 4] = make_uint4(v[0], v[1], v[2], v[3]);
    }
}

// ---------------- k2: gaussian splat, warp per point ----------------
__global__ void draw_kernel(const void* __restrict__ rcoors,
                            const float* __restrict__ rcs,
                            const float* __restrict__ gamma_p,
                            int N) {
    int p = blockIdx.x * 8 + (threadIdx.x >> 5);
    if (p >= N) return;
    int lane = threadIdx.x & 31;
    int is64 = g_coor64;
    int b, y, x;
    if (is64) {
        const long long* r8 = (const long long*)rcoors;
        b = (int)r8[p * 4 + 0]; y = (int)r8[p * 4 + 2]; x = (int)r8[p * 4 + 3];
    } else {
        const int* r4 = (const int*)rcoors;
        b = r4[p * 4 + 0]; y = r4[p * 4 + 2]; x = r4[p * 4 + 3];
    }
    float t = fmaxf(rcs[p], 0.0f);
    float gamma = *gamma_p;
    float r = floorf(gamma * t + 1.0f);
    float sigma = (2.0f * r + 1.0f) / 6.0f;
    float inv2s2 = 1.0f / (2.0f * sigma * sigma);
    int ri = (int)r;
    if (ri > HW) ri = HW;
    int side = 2 * ri + 1;
    int tot = side * side;
    const float EPS = 1.1920929e-7f;
    for (int idx = lane; idx < tot; idx += 32) {
        int dy = idx / side - ri;
        int dx = idx % side - ri;
        int py = y + dy, px = x + dx;
        if ((unsigned)py < HW && (unsigned)px < HW) {
            float d2 = (float)(dy * dy + dx * dx);
            float g = __expf(-d2 * inv2s2);
            if (g >= EPS) {
                int off = b * (HW * HW) + py * HW + px;
                atomicMax((int*)&g_hm[off],  __float_as_int(g));
                atomicMax((int*)&g_hmf[off], __float_as_int(g * t));
            }
        }
    }
}

// ---------------- k3: mma.sync conv, 2 output rows per CTA ----------------
#define SM_RB0H 0
#define SM_RB0L 18720
#define SM_RB1H 37440
#define SM_RB1L 56160
#define SM_EAH  74880
#define SM_EAL  85120
#define SMEM_TOTAL 95360
#define RB_STRIDE 144
#define EA_STRIDE 80
#define NTHREADS 256

__global__ void __launch_bounds__(NTHREADS, 2)
conv_mma_kernel(const float* __restrict__ lidar,
                const float* __restrict__ comp_b,
                float* __restrict__ out) {
    extern __shared__ char smc[];
    uint32_t sb = smem_u32(smc);
    const int tid  = threadIdx.x;
    const int wid  = tid >> 5;
    const int lane = tid & 31;
    const int y0 = blockIdx.x * 2;
    const int b  = blockIdx.y;

    // ---- zero guard rows 0 / 129 of both row buffers (hi+lo) ----
    if (tid < 144) {
        int reg = tid / 36;                  // RB0H,RB0L,RB1H,RB1L
        int w = tid - reg * 36;
        uint32_t base = reg * 18720;
        *(uint32_t*)(smc + base + 0 * RB_STRIDE + w * 4)   = 0;
        *(uint32_t*)(smc + base + 129 * RB_STRIDE + w * 4) = 0;
    }

    const float* lid_b = lidar + (size_t)b * C_MID * HW * HW;
    const float* hm_b  = g_hm  + b * HW * HW;
    const float* hmf_b = g_hmf + b * HW * HW;

    // ---- prologue: build row (y0-1) into buffer 0 ----
    if (y0 - 1 >= 0) {
        const float* rp = lid_b + (size_t)(y0 - 1) * HW;
        #pragma unroll
        for (int k = 0; k < 16; k++) {
            int i = tid + k * NTHREADS;
            int px = i & 127, cp = i >> 7;
            float v0 = rp[(size_t)(2 * cp) * (HW * HW) + px];
            float v1 = rp[(size_t)(2 * cp + 1) * (HW * HW) + px];
            uint32_t lp, hp = pack_hl(v0, v1, lp);
            *(uint32_t*)(smc + SM_RB0H + (px + 1) * RB_STRIDE + cp * 4) = hp;
            *(uint32_t*)(smc + SM_RB0L + (px + 1) * RB_STRIDE + cp * 4) = lp;
        }
    }

    // ---- build extra-channel A for row y0 ----
    {
        int y = y0;
        #pragma unroll 1
        for (int i = tid; i < 2048; i += NTHREADS) {
            int px = i & 127;
            int sp = i >> 7;
            float v[2];
            #pragma unroll
            for (int u = 0; u < 2; u++) {
                int slot = sp * 2 + u;
                float val = 0.f;
                if (slot < 27) {
                    int tap = slot / 3, j = slot - 3 * tap;
                    int kyy = tap / 3, kxx = tap - 3 * kyy;
                    int ry = y + kyy - 1, rx = px + kxx - 1;
                    if ((unsigned)ry < HW && (unsigned)rx < HW) {
                        if (j == 0)      val = hm_b[ry * HW + rx];
                        else if (j == 1) val = hmf_b[ry * HW + rx];
                        else             val = 1.0f;
                    }
                }
                v[u] = val;
            }
            uint32_t lp, hp = pack_hl(v[0], v[1], lp);
            *(uint32_t*)(smc + SM_EAH + px * EA_STRIDE + sp * 4) = hp;
            *(uint32_t*)(smc + SM_EAL + px * EA_STRIDE + sp * 4) = lp;
        }
    }
    __syncthreads();

    // ---- accumulators: 2 rows x 2 m-tiles x 4 n-tiles ----
    float acc[2][2][4][4];
    #pragma unroll
    for (int rw = 0; rw < 2; rw++)
        #pragma unroll
        for (int mt = 0; mt < 2; mt++)
            #pragma unroll
            for (int t = 0; t < 4; t++)
                #pragma unroll
                for (int j = 0; j < 4; j++) acc[rw][mt][t][j] = 0.f;

    const int h   = wid & 1;           // oc half
    const int px0 = (wid >> 1) * 32;   // 32-px group
    const uint32_t row_add = (lane & 7) + ((lane >> 3) & 1) * 8;
    const uint32_t a_half  = (lane >> 4) * 16;

    const uint4* wf4 = (const uint4*)g_wfrag;
    const uint4* ef4 = (const uint4*)g_efrag;
    const int wbase = (2 * h) * 256 + lane;
    const int ebase = (2 * h) * 128 + lane;

    // ---- EA MMA for row y0 ----
    {
        uint32_t a0 = sb + SM_EAH + (px0 + row_add) * EA_STRIDE + a_half;
        #pragma unroll
        for (int kc = 0; kc < 2; kc++) {
            uint32_t Ah[2][4], Al[2][4];
            #pragma unroll
            for (int mt = 0; mt < 2; mt++) {
                uint32_t aH = a0 + mt * (16 * EA_STRIDE) + kc * 32;
                ldsm_x4(aH, Ah[mt][0], Ah[mt][1], Ah[mt][2], Ah[mt][3]);
                ldsm_x4(aH + (SM_EAL - SM_EAH), Al[mt][0], Al[mt][1], Al[mt][2], Al[mt][3]);
            }
            #pragma unroll
            for (int nbp = 0; nbp < 2; nbp++) {
                uint4 bh = ef4[ebase + nbp * 128 + kc * 64];
                uint4 bl = ef4[ebase + nbp * 128 + kc * 64 + 32];
                #pragma unroll
                for (int mt = 0; mt < 2; mt++) {
                    mma_bf16(acc[0][mt][2 * nbp],     Ah[mt], bh.x, bh.y);
                    mma_bf16(acc[0][mt][2 * nbp + 1], Ah[mt], bh.z, bh.w);
                    mma_bf16(acc[0][mt][2 * nbp],     Ah[mt], bl.x, bl.y);
                    mma_bf16(acc[0][mt][2 * nbp + 1], Ah[mt], bl.z, bl.w);
                    mma_bf16(acc[0][mt][2 * nbp],     Al[mt], bh.x, bh.y);
                    mma_bf16(acc[0][mt][2 * nbp + 1], Al[mt], bh.z, bh.w);
                }
            }
        }
    }

    // ---- 4 input-row phases; phase s = input row y0-1+s in buffer s&1 ----
    #pragma unroll 1
    for (int s = 0; s < 4; s++) {
        int ry = y0 - 1 + s;
        int vcur = ((unsigned)ry < HW);
        int vnext = (s < 3) && ((y0 + s) < HW);

        // prefetch first half of next row
        float pf0[8], pf1[8];
        if (vnext) {
            const float* rp = lid_b + (size_t)(y0 + s) * HW;
            #pragma unroll
            for (int k = 0; k < 8; k++) {
                int i = tid + k * NTHREADS;
                int px = i & 127, cp = i >> 7;
                pf0[k] = rp[(size_t)(2 * cp) * (HW * HW) + px];
                pf1[k] = rp[(size_t)(2 * cp + 1) * (HW * HW) + px];
            }
        }

        if (vcur) {
            uint32_t bufH = (s & 1) ? SM_RB1H : SM_RB0H;
            int g0 = (s <= 2);            // row y0, tap ky=s
            int g1 = (s >= 1);            // row y1, tap ky=s-1
            #pragma unroll
            for (int kx = 0; kx < 3; kx++) {
                uint32_t a0 = sb + bufH + (px0 + kx + row_add) * RB_STRIDE + a_half;
                const uint4* wt0 = wf4 + (s * 3 + kx) * 1024 + wbase;
                const uint4* wt1 = wf4 + ((s - 1) * 3 + kx) * 1024 + wbase;
                #pragma unroll
                for (int kc = 0; kc < 4; kc++) {
                    uint32_t Ah[2][4], Al[2][4];
                    #pragma unroll
                    for (int mt = 0; mt < 2; mt++) {
                        uint32_t aH = a0 + mt * (16 * RB_STRIDE) + kc * 32;
                        ldsm_x4(aH, Ah[mt][0], Ah[mt][1], Ah[mt][2], Ah[mt][3]);
                        ldsm_x4(aH + 18720, Al[mt][0], Al[mt][1], Al[mt][2], Al[mt][3]);
                    }
                    #pragma unroll
                    for (int nbp = 0; nbp < 2; nbp++) {
                        if (g0) {
                            uint4 bh = wt0[nbp * 256 + kc * 64];
                            uint4 bl = wt0[nbp * 256 + kc * 64 + 32];
                            #pragma unroll
                            for (int mt = 0; mt < 2; mt++) {
                                mma_bf16(acc[0][mt][2 * nbp],     Ah[mt], bh.x, bh.y);
                                mma_bf16(acc[0][mt][2 * nbp + 1], Ah[mt], bh.z, bh.w);
                                mma_bf16(acc[0][mt][2 * nbp],     Ah[mt], bl.x, bl.y);
                                mma_bf16(acc[0][mt][2 * nbp + 1], Ah[mt], bl.z, bl.w);
                                mma_bf16(acc[0][mt][2 * nbp],     Al[mt], bh.x, bh.y);
                                mma_bf16(acc[0][mt][2 * nbp + 1], Al[mt], bh.z, bh.w);
                            }
                        }
                        if (g1) {
                            uint4 bh = wt1[nbp * 256 + kc * 64];
                            uint4 bl = wt1[nbp * 256 + kc * 64 + 32];
                            #pragma unroll
                            for (int mt = 0; mt < 2; mt++) {
                                mma_bf16(acc[1][mt][2 * nbp],     Ah[mt], bh.x, bh.y);
                                mma_bf16(acc[1][mt][2 * nbp + 1], Ah[mt], bh.z, bh.w);
                                mma_bf16(acc[1][mt][2 * nbp],     Ah[mt], bl.x, bl.y);
                                mma_bf16(acc[1][mt][2 * nbp + 1], Ah[mt], bl.z, bl.w);
                                mma_bf16(acc[1][mt][2 * nbp],     Al[mt], bh.x, bh.y);
                                mma_bf16(acc[1][mt][2 * nbp + 1], Al[mt], bh.z, bh.w);
                            }
                        }
                    }
                }
            }
        }

        if (s < 3) {
            if (vnext) {
                uint32_t dH = ((s + 1) & 1) ? SM_RB1H : SM_RB0H;
                uint32_t dL = dH + 18720;
                // round 0: from prefetch regs (cp 0..15)
                #pragma unroll
                for (int k = 0; k < 8; k++) {
                    int i = tid + k * NTHREADS;
                    int px = i & 127, cp = i >> 7;
                    uint32_t lp, hp = pack_hl(pf0[k], pf1[k], lp);
                    *(uint32_t*)(smc + dH + (px + 1) * RB_STRIDE + cp * 4) = hp;
                    *(uint32_t*)(smc + dL + (px + 1) * RB_STRIDE + cp * 4) = lp;
                }
                // round 1: direct load+store (cp 16..31)
                const float* rp = lid_b + (size_t)(y0 + s) * HW;
                #pragma unroll
                for (int k = 8; k < 16; k++) {
                    int i = tid + k * NTHREADS;
                    int px = i & 127, cp = i >> 7;
                    float v0 = rp[(size_t)(2 * cp) * (HW * HW) + px];
                    float v1 = rp[(size_t)(2 * cp + 1) * (HW * HW) + px];
                    uint32_t lp, hp = pack_hl(v0, v1, lp);
                    *(uint32_t*)(smc + dH + (px + 1) * RB_STRIDE + cp * 4) = hp;
                    *(uint32_t*)(smc + dL + (px + 1) * RB_STRIDE + cp * 4) = lp;
                }
            }
            __syncthreads();
        }
    }

    // ---- rebuild EA for row y1, then EA MMA ----
    {
        int y = y0 + 1;
        #pragma unroll 1
        for (int i = tid; i < 2048; i += NTHREADS) {
            int px = i & 127;
            int sp = i >> 7;
            float v[2];
            #pragma unroll
            for (int u = 0; u < 2; u++) {
                int slot = sp * 2 + u;
                float val = 0.f;
                if (slot < 27) {
                    int tap = slot / 3, j = slot - 3 * tap;
                    int kyy = tap / 3, kxx = tap - 3 * kyy;
                    int ry = y + kyy - 1, rx = px + kxx - 1;
                    if ((unsigned)ry < HW && (unsigned)rx < HW) {
                        if (j == 0)      val = hm_b[ry * HW + rx];
                        else if (j == 1) val = hmf_b[ry * HW + rx];
                        else             val = 1.0f;
                    }
                }
                v[u] = val;
            }
            uint32_t lp, hp = pack_hl(v[0], v[1], lp);
            *(uint32_t*)(smc + SM_EAH + px * EA_STRIDE + sp * 4) = hp;
            *(uint32_t*)(smc + SM_EAL + px * EA_STRIDE + sp * 4) = lp;
        }
    }
    __syncthreads();
    {
        uint32_t a0 = sb + SM_EAH + (px0 + row_add) * EA_STRIDE + a_half;
        #pragma unroll
        for (int kc = 0; kc < 2; kc++) {
            uint32_t Ah[2][4], Al[2][4];
            #pragma unroll
            for (int mt = 0; mt < 2; mt++) {
                uint32_t aH = a0 + mt * (16 * EA_STRIDE) + kc * 32;
                ldsm_x4(aH, Ah[mt][0], Ah[mt][1], Ah[mt][2], Ah[mt][3]);
                ldsm_x4(aH + (SM_EAL - SM_EAH), Al[mt][0], Al[mt][1], Al[mt][2], Al[mt][3]);
            }
            #pragma unroll
            for (int nbp = 0; nbp < 2; nbp++) {
                uint4 bh = ef4[ebase + nbp * 128 + kc * 64];
                uint4 bl = ef4[ebase + nbp * 128 + kc * 64 + 32];
                #pragma unroll
                for (int mt = 0; mt < 2; mt++) {
                    mma_bf16(acc[1][mt][2 * nbp],     Ah[mt], bh.x, bh.y);
                    mma_bf16(acc[1][mt][2 * nbp + 1], Ah[mt], bh.z, bh.w);
                    mma_bf16(acc[1][mt][2 * nbp],     Ah[mt], bl.x, bl.y);
                    mma_bf16(acc[1][mt][2 * nbp + 1], Ah[mt], bl.z, bl.w);
                    mma_bf16(acc[1][mt][2 * nbp],     Al[mt], bh.x, bh.y);
                    mma_bf16(acc[1][mt][2 * nbp + 1], Al[mt], bh.z, bh.w);
                }
            }
        }
    }

    // ---- epilogues: both rows ----
    #pragma unroll
    for (int rw = 0; rw < 2; rw++) {
        int y = y0 + rw;
        #pragma unroll
        for (int mt = 0; mt < 2; mt++) {
            int r0 = px0 + mt * 16 + (lane >> 2);
            #pragma unroll
            for (int nt = 0; nt < 4; nt++) {
                int oc = h * 32 + nt * 8 + (lane & 3) * 2;
                float bv0 = comp_b[oc], bv1 = comp_b[oc + 1];
                float* o0 = out + (((size_t)b * 64 + oc) * HW + y) * HW;
                float* o1 = o0 + (size_t)HW * HW;
                o0[r0]     = acc[rw][mt][nt][0] + bv0;
                o1[r0]     = acc[rw][mt][nt][1] + bv1;
                o0[r0 + 8] = acc[rw][mt][nt][2] + bv0;
                o1[r0 + 8] = acc[rw][mt][nt][3] + bv1;
            }
        }
    }
}

// ---------------- launch ----------------
extern "C" void kernel_launch(void* const* d_in, const int* in_sizes, int n_in,
                              void* d_out, int out_size) {
    const float* lidar  = (const float*)d_in[0];
    const void*  rcoors = d_in[2];
    const float* rcs    = (const float*)d_in[4];
    const float* gamma  = (const float*)d_in[5];
    const float* att_w  = (const float*)d_in[6];
    const float* att_b  = (const float*)d_in[7];
    const float* comp_w = (const float*)d_in[8];
    const float* comp_b = (const float*)d_in[9];
    float* out = (float*)d_out;

    int B = in_sizes[0] / (C_MID * HW * HW);
    if (B < 1) B = 1; if (B > MAXB) B = MAXB;
    int N = in_sizes[4];

    // k1: setup (init + detect + fragments)
    int nz = B * HW * HW;
    int init_blocks = (nz + 255) / 256;
    setup_kernel<<<init_blocks + 38, 256>>>((const int*)rcoors, comp_w, att_w, att_b,
                                            nz, init_blocks);

    // k2: draw
    draw_kernel<<<(N + 7) / 8, 256>>>(rcoors, rcs, gamma, N);

    // k3: conv (2 rows per CTA)
    cudaFuncSetAttribute(conv_mma_kernel,
                         cudaFuncAttributeMaxDynamicSharedMemorySize, SMEM_TOTAL);
    dim3 grid(HW / 2, B);
    conv_mma_kernel<<<grid, NTHREADS, SMEM_TOTAL>>>(lidar, comp_b, out);
}

// round 17
// speedup vs baseline: 1.4880x; 1.4880x over previous
#include <cuda_runtime.h>
#include <cuda_bf16.h>
#include <math.h>
#include <stdint.h>

#define HW 128
#define C_MID 64
#define MAXB 8

// ---------------- scratch (no allocs allowed) ----------------
__device__ float g_hm [MAXB * HW * HW];
__device__ float g_hmf[MAXB * HW * HW];
// main weight fragments, mma-B register layout:
// [tap(9)][npair(4)][kc(4)][hl(2)][lane(32)][reg(4)] uint32
__device__ __align__(16) uint32_t g_wfrag[9 * 4 * 4 * 2 * 32 * 4];
// extra-channel fragments: [npair(4)][kc(2)][hl(2)][lane(32)][reg(4)]
__device__ __align__(16) uint32_t g_efrag[4 * 2 * 2 * 32 * 4];
// extra-channel folded sums [oc(64)][slot(32)]
__device__ float g_esum[64 * 32];
__device__ int g_coor64;

// ---------------- helpers ----------------
__device__ __forceinline__ uint32_t smem_u32(const void* p) {
    uint32_t a;
    asm("{ .reg .u64 t; cvta.to.shared.u64 t, %1; cvt.u32.u64 %0, t; }" : "=r"(a) : "l"(p));
    return a;
}
__device__ __forceinline__ void ldsm_x4(uint32_t addr, uint32_t& r0, uint32_t& r1,
                                        uint32_t& r2, uint32_t& r3) {
    asm volatile("ldmatrix.sync.aligned.m8n8.x4.shared.b16 {%0,%1,%2,%3}, [%4];"
                 : "=r"(r0), "=r"(r1), "=r"(r2), "=r"(r3) : "r"(addr));
}
__device__ __forceinline__ void mma_bf16(float* d, const uint32_t* a,
                                         uint32_t b0, uint32_t b1) {
    asm volatile(
        "mma.sync.aligned.m16n8k16.row.col.f32.bf16.bf16.f32 "
        "{%0,%1,%2,%3},{%4,%5,%6,%7},{%8,%9},{%0,%1,%2,%3};"
        : "+f"(d[0]), "+f"(d[1]), "+f"(d[2]), "+f"(d[3])
        : "r"(a[0]), "r"(a[1]), "r"(a[2]), "r"(a[3]), "r"(b0), "r"(b1));
}
__device__ __forceinline__ uint32_t pack_hl(float v0, float v1, uint32_t& lo) {
    __nv_bfloat16 h0 = __float2bfloat16(v0);
    __nv_bfloat16 h1 = __float2bfloat16(v1);
    __nv_bfloat16 l0 = __float2bfloat16(v0 - __bfloat162float(h0));
    __nv_bfloat16 l1 = __float2bfloat16(v1 - __bfloat162float(h1));
    lo = (uint32_t)__bfloat16_as_ushort(l0) | ((uint32_t)__bfloat16_as_ushort(l1) << 16);
    return (uint32_t)__bfloat16_as_ushort(h0) | ((uint32_t)__bfloat16_as_ushort(h1) << 16);
}
__device__ __forceinline__ uint32_t pack_sel(float v0, float v1, int hl) {
    uint32_t lo, hi = pack_hl(v0, v1, lo);
    return hl ? lo : hi;
}

// ---------------- k1: detect + fold_a ----------------
__global__ void detect_fold_a_kernel(const int* __restrict__ rc_as_i32,
                                     const float* __restrict__ comp_w,
                                     const float* __restrict__ att_w,
                                     const float* __restrict__ att_b) {
    int t = blockIdx.x * blockDim.x + threadIdx.x;
    if (t == 0) {
        int all0 = 1;
        #pragma unroll 1
        for (int i = 1; i < 128; i += 2) all0 &= (rc_as_i32[i] == 0);
        g_coor64 = all0;
    }
    if (t >= 64 * 9) return;
    int o = t / 9, tap = t % 9;
    float s0 = 0.f, s1 = 0.f, s2 = 0.f;
    #pragma unroll 4
    for (int c = 0; c < 64; c++) {
        float w = comp_w[(o * 128 + 64 + c) * 9 + tap];
        s0 += w * att_w[2 * c];
        s1 += w * att_w[2 * c + 1];
        s2 += w * att_b[c];
    }
    g_esum[o * 32 + tap * 3 + 0] = s0;
    g_esum[o * 32 + tap * 3 + 1] = s1;
    g_esum[o * 32 + tap * 3 + 2] = s2;
    if (tap == 0)
        for (int s = 27; s < 32; s++) g_esum[o * 32 + s] = 0.f;
}

// ---------------- k2: init heatmaps + fold_b fragments ----------------
__global__ void init_fold_b_kernel(const float* __restrict__ comp_w,
                                   int nz, int init_blocks) {
    if ((int)blockIdx.x < init_blocks) {
        int i = blockIdx.x * blockDim.x + threadIdx.x;
        if (i < nz) { g_hm[i] = 0.0f; g_hmf[i] = 0.0f; }
        return;
    }
    int t = (blockIdx.x - init_blocks) * blockDim.x + threadIdx.x;
    if (t < 9216) {               // main: [tap][npair][kc][hl][lane]
        int lane = t & 31;
        int r = t >> 5;
        int hl = r & 1;
        int kc = (r >> 1) & 3;
        int npair = (r >> 3) & 3;
        int tap = r >> 5;
        uint32_t v[4];
        #pragma unroll
        for (int m = 0; m < 4; m++) {
            int nb = 2 * npair + (m >> 1);
            int oc = nb * 8 + (lane >> 2);
            int k0 = kc * 16 + (m & 1) * 8 + 2 * (lane & 3);
            float w0 = comp_w[(oc * 128 + k0) * 9 + tap];
            float w1 = comp_w[(oc * 128 + k0 + 1) * 9 + tap];
            v[m] = pack_sel(w0, w1, hl);
        }
        *(uint4*)&g_wfrag[t * 4] = make_uint4(v[0], v[1], v[2], v[3]);
    } else if (t < 9216 + 512) {  // extra: [npair][kc][hl][lane]
        int e = t - 9216;
        int lane = e & 31;
        int r = e >> 5;
        int hl = r & 1;
        int kc = (r >> 1) & 1;
        int npair = r >> 2;
        uint32_t v[4];
        #pragma unroll
        for (int m = 0; m < 4; m++) {
            int nb = 2 * npair + (m >> 1);
            int oc = nb * 8 + (lane >> 2);
            int s0 = kc * 16 + (m & 1) * 8 + 2 * (lane & 3);
            float w0 = g_esum[oc * 32 + s0];
            float w1 = g_esum[oc * 32 + s0 + 1];
            v[m] = pack_sel(w0, w1, hl);
        }
        *(uint4*)&g_efrag[e * 4] = make_uint4(v[0], v[1], v[2], v[3]);
    }
}

// ---------------- k3: gaussian splat, warp per point ----------------
__global__ void draw_kernel(const void* __restrict__ rcoors,
                            const float* __restrict__ rcs,
                            const float* __restrict__ gamma_p,
                            int N) {
    int p = blockIdx.x * 8 + (threadIdx.x >> 5);
    if (p >= N) return;
    int lane = threadIdx.x & 31;
    int is64 = g_coor64;
    int b, y, x;
    if (is64) {
        const long long* r8 = (const long long*)rcoors;
        b = (int)r8[p * 4 + 0]; y = (int)r8[p * 4 + 2]; x = (int)r8[p * 4 + 3];
    } else {
        const int* r4 = (const int*)rcoors;
        b = r4[p * 4 + 0]; y = r4[p * 4 + 2]; x = r4[p * 4 + 3];
    }
    float t = fmaxf(rcs[p], 0.0f);
    float gamma = *gamma_p;
    float r = floorf(gamma * t + 1.0f);
    float sigma = (2.0f * r + 1.0f) / 6.0f;
    float inv2s2 = 1.0f / (2.0f * sigma * sigma);
    int ri = (int)r;
    if (ri > HW) ri = HW;
    int side = 2 * ri + 1;
    int tot = side * side;
    const float EPS = 1.1920929e-7f;
    for (int idx = lane; idx < tot; idx += 32) {
        int dy = idx / side - ri;
        int dx = idx % side - ri;
        int py = y + dy, px = x + dx;
        if ((unsigned)py < HW && (unsigned)px < HW) {
            float d2 = (float)(dy * dy + dx * dx);
            float g = expf(-d2 * inv2s2);
            if (g >= EPS) {
                int off = b * (HW * HW) + py * HW + px;
                atomicMax((int*)&g_hm[off],  __float_as_int(g));
                atomicMax((int*)&g_hmf[off], __float_as_int(g * t));
            }
        }
    }
}

// ---------------- k4: mma.sync conv, 2 output rows per CTA ----------------
#define SM_RB0H 0
#define SM_RB0L 18720
#define SM_RB1H 37440
#define SM_RB1L 56160
#define SM_EAH  74880
#define SM_EAL  85120
#define SMEM_TOTAL 95360
#define RB_STRIDE 144
#define EA_STRIDE 80
#define NTHREADS 256

__global__ void __launch_bounds__(NTHREADS, 2)
conv_mma_kernel(const float* __restrict__ lidar,
                const float* __restrict__ comp_b,
                float* __restrict__ out) {
    extern __shared__ char smc[];
    uint32_t sb = smem_u32(smc);
    const int tid  = threadIdx.x;
    const int wid  = tid >> 5;
    const int lane = tid & 31;
    const int y0 = blockIdx.x * 2;
    const int b  = blockIdx.y;

    // ---- zero guard rows 0 / 129 of both row buffers (hi+lo) ----
    if (tid < 144) {
        int reg = tid / 36;                  // RB0H,RB0L,RB1H,RB1L
        int w = tid - reg * 36;
        uint32_t base = reg * 18720;
        *(uint32_t*)(smc + base + 0 * RB_STRIDE + w * 4)   = 0;
        *(uint32_t*)(smc + base + 129 * RB_STRIDE + w * 4) = 0;
    }

    const float* lid_b = lidar + (size_t)b * C_MID * HW * HW;
    const float* hm_b  = g_hm  + b * HW * HW;
    const float* hmf_b = g_hmf + b * HW * HW;

    // ---- prologue: build row (y0-1) into buffer 0 ----
    if (y0 - 1 >= 0) {
        const float* rp = lid_b + (size_t)(y0 - 1) * HW;
        #pragma unroll
        for (int k = 0; k < 16; k++) {
            int i = tid + k * NTHREADS;
            int px = i & 127, cp = i >> 7;
            float v0 = rp[(size_t)(2 * cp) * (HW * HW) + px];
            float v1 = rp[(size_t)(2 * cp + 1) * (HW * HW) + px];
            uint32_t lp, hp = pack_hl(v0, v1, lp);
            *(uint32_t*)(smc + SM_RB0H + (px + 1) * RB_STRIDE + cp * 4) = hp;
            *(uint32_t*)(smc + SM_RB0L + (px + 1) * RB_STRIDE + cp * 4) = lp;
        }
    }

    // ---- build extra-channel A for row y0 ----
    {
        int y = y0;
        #pragma unroll 1
        for (int i = tid; i < 2048; i += NTHREADS) {
            int px = i & 127;
            int sp = i >> 7;
            float v[2];
            #pragma unroll
            for (int u = 0; u < 2; u++) {
                int slot = sp * 2 + u;
                float val = 0.f;
                if (slot < 27) {
                    int tap = slot / 3, j = slot - 3 * tap;
                    int kyy = tap / 3, kxx = tap - 3 * kyy;
                    int ry = y + kyy - 1, rx = px + kxx - 1;
                    if ((unsigned)ry < HW && (unsigned)rx < HW) {
                        if (j == 0)      val = hm_b[ry * HW + rx];
                        else if (j == 1) val = hmf_b[ry * HW + rx];
                        else             val = 1.0f;
                    }
                }
                v[u] = val;
            }
            uint32_t lp, hp = pack_hl(v[0], v[1], lp);
            *(uint32_t*)(smc + SM_EAH + px * EA_STRIDE + sp * 4) = hp;
            *(uint32_t*)(smc + SM_EAL + px * EA_STRIDE + sp * 4) = lp;
        }
    }
    __syncthreads();

    // ---- accumulators: 2 rows x 2 m-tiles x 4 n-tiles ----
    float acc[2][2][4][4];
    #pragma unroll
    for (int rw = 0; rw < 2; rw++)
        #pragma unroll
        for (int mt = 0; mt < 2; mt++)
            #pragma unroll
            for (int t = 0; t < 4; t++)
                #pragma unroll
                for (int j = 0; j < 4; j++) acc[rw][mt][t][j] = 0.f;

    const int h   = wid & 1;           // oc half
    const int px0 = (wid >> 1) * 32;   // 32-px group
    const uint32_t row_add = (lane & 7) + ((lane >> 3) & 1) * 8;
    const uint32_t a_half  = (lane >> 4) * 16;

    const uint4* wf4 = (const uint4*)g_wfrag;
    const uint4* ef4 = (const uint4*)g_efrag;
    const int wbase = (2 * h) * 256 + lane;
    const int ebase = (2 * h) * 128 + lane;

    // ---- EA MMA for row y0 ----
    {
        uint32_t a0 = sb + SM_EAH + (px0 + row_add) * EA_STRIDE + a_half;
        #pragma unroll
        for (int kc = 0; kc < 2; kc++) {
            uint32_t Ah[2][4], Al[2][4];
            #pragma unroll
            for (int mt = 0; mt < 2; mt++) {
                uint32_t aH = a0 + mt * (16 * EA_STRIDE) + kc * 32;
                ldsm_x4(aH, Ah[mt][0], Ah[mt][1], Ah[mt][2], Ah[mt][3]);
                ldsm_x4(aH + (SM_EAL - SM_EAH), Al[mt][0], Al[mt][1], Al[mt][2], Al[mt][3]);
            }
            #pragma unroll
            for (int nbp = 0; nbp < 2; nbp++) {
                uint4 bh = ef4[ebase + nbp * 128 + kc * 64];
                uint4 bl = ef4[ebase + nbp * 128 + kc * 64 + 32];
                #pragma unroll
                for (int mt = 0; mt < 2; mt++) {
                    mma_bf16(acc[0][mt][2 * nbp],     Ah[mt], bh.x, bh.y);
                    mma_bf16(acc[0][mt][2 * nbp + 1], Ah[mt], bh.z, bh.w);
                    mma_bf16(acc[0][mt][2 * nbp],     Ah[mt], bl.x, bl.y);
                    mma_bf16(acc[0][mt][2 * nbp + 1], Ah[mt], bl.z, bl.w);
                    mma_bf16(acc[0][mt][2 * nbp],     Al[mt], bh.x, bh.y);
                    mma_bf16(acc[0][mt][2 * nbp + 1], Al[mt], bh.z, bh.w);
                }
            }
        }
    }

    // ---- 4 input-row phases; phase s = input row y0-1+s in buffer s&1 ----
    #pragma unroll 1
    for (int s = 0; s < 4; s++) {
        int ry = y0 - 1 + s;
        int vcur = ((unsigned)ry < HW);
        int vnext = (s < 3) && ((y0 + s) < HW);

        // prefetch first half of next row
        float pf0[8], pf1[8];
        if (vnext) {
            const float* rp = lid_b + (size_t)(y0 + s) * HW;
            #pragma unroll
            for (int k = 0; k < 8; k++) {
                int i = tid + k * NTHREADS;
                int px = i & 127, cp = i >> 7;
                pf0[k] = rp[(size_t)(2 * cp) * (HW * HW) + px];
                pf1[k] = rp[(size_t)(2 * cp + 1) * (HW * HW) + px];
            }
        }

        if (vcur) {
            uint32_t bufH = (s & 1) ? SM_RB1H : SM_RB0H;
            int g0 = (s <= 2);            // row y0, tap ky=s
            int g1 = (s >= 1);            // row y1, tap ky=s-1
            #pragma unroll
            for (int kx = 0; kx < 3; kx++) {
                uint32_t a0 = sb + bufH + (px0 + kx + row_add) * RB_STRIDE + a_half;
                const uint4* wt0 = wf4 + (s * 3 + kx) * 1024 + wbase;
                const uint4* wt1 = wf4 + ((s - 1) * 3 + kx) * 1024 + wbase;
                #pragma unroll
                for (int kc = 0; kc < 4; kc++) {
                    uint32_t Ah[2][4], Al[2][4];
                    #pragma unroll
                    for (int mt = 0; mt < 2; mt++) {
                        uint32_t aH = a0 + mt * (16 * RB_STRIDE) + kc * 32;
                        ldsm_x4(aH, Ah[mt][0], Ah[mt][1], Ah[mt][2], Ah[mt][3]);
                        ldsm_x4(aH + 18720, Al[mt][0], Al[mt][1], Al[mt][2], Al[mt][3]);
                    }
                    #pragma unroll
                    for (int nbp = 0; nbp < 2; nbp++) {
                        if (g0) {
                            uint4 bh = wt0[nbp * 256 + kc * 64];
                            uint4 bl = wt0[nbp * 256 + kc * 64 + 32];
                            #pragma unroll
                            for (int mt = 0; mt < 2; mt++) {
                                mma_bf16(acc[0][mt][2 * nbp],     Ah[mt], bh.x, bh.y);
                                mma_bf16(acc[0][mt][2 * nbp + 1], Ah[mt], bh.z, bh.w);
                                mma_bf16(acc[0][mt][2 * nbp],     Ah[mt], bl.x, bl.y);
                                mma_bf16(acc[0][mt][2 * nbp + 1], Ah[mt], bl.z, bl.w);
                                mma_bf16(acc[0][mt][2 * nbp],     Al[mt], bh.x, bh.y);
                                mma_bf16(acc[0][mt][2 * nbp + 1], Al[mt], bh.z, bh.w);
                            }
                        }
                        if (g1) {
                            uint4 bh = wt1[nbp * 256 + kc * 64];
                            uint4 bl = wt1[nbp * 256 + kc * 64 + 32];
                            #pragma unroll
                            for (int mt = 0; mt < 2; mt++) {
                                mma_bf16(acc[1][mt][2 * nbp],     Ah[mt], bh.x, bh.y);
                                mma_bf16(acc[1][mt][2 * nbp + 1], Ah[mt], bh.z, bh.w);
                                mma_bf16(acc[1][mt][2 * nbp],     Ah[mt], bl.x, bl.y);
                                mma_bf16(acc[1][mt][2 * nbp + 1], Ah[mt], bl.z, bl.w);
                                mma_bf16(acc[1][mt][2 * nbp],     Al[mt], bh.x, bh.y);
                                mma_bf16(acc[1][mt][2 * nbp + 1], Al[mt], bh.z, bh.w);
                            }
                        }
                    }
                }
            }
        }

        if (s < 3) {
            if (vnext) {
                uint32_t dH = ((s + 1) & 1) ? SM_RB1H : SM_RB0H;
                uint32_t dL = dH + 18720;
                // round 0: from prefetch regs (cp 0..15)
                #pragma unroll
                for (int k = 0; k < 8; k++) {
                    int i = tid + k * NTHREADS;
                    int px = i & 127, cp = i >> 7;
                    uint32_t lp, hp = pack_hl(pf0[k], pf1[k], lp);
                    *(uint32_t*)(smc + dH + (px + 1) * RB_STRIDE + cp * 4) = hp;
                    *(uint32_t*)(smc + dL + (px + 1) * RB_STRIDE + cp * 4) = lp;
                }
                // round 1: direct load+store (cp 16..31)
                const float* rp = lid_b + (size_t)(y0 + s) * HW;
                #pragma unroll
                for (int k = 8; k < 16; k++) {
                    int i = tid + k * NTHREADS;
                    int px = i & 127, cp = i >> 7;
                    float v0 = rp[(size_t)(2 * cp) * (HW * HW) + px];
                    float v1 = rp[(size_t)(2 * cp + 1) * (HW * HW) + px];
                    uint32_t lp, hp = pack_hl(v0, v1, lp);
                    *(uint32_t*)(smc + dH + (px + 1) * RB_STRIDE + cp * 4) = hp;
                    *(uint32_t*)(smc + dL + (px + 1) * RB_STRIDE + cp * 4) = lp;
                }
            }
            __syncthreads();
        }
    }

    // ---- rebuild EA for row y1, then EA MMA ----
    {
        int y = y0 + 1;
        #pragma unroll 1
        for (int i = tid; i < 2048; i += NTHREADS) {
            int px = i & 127;
            int sp = i >> 7;
            float v[2];
            #pragma unroll
            for (int u = 0; u < 2; u++) {
                int slot = sp * 2 + u;
                float val = 0.f;
                if (slot < 27) {
                    int tap = slot / 3, j = slot - 3 * tap;
                    int kyy = tap / 3, kxx = tap - 3 * kyy;
                    int ry = y + kyy - 1, rx = px + kxx - 1;
                    if ((unsigned)ry < HW && (unsigned)rx < HW) {
                        if (j == 0)      val = hm_b[ry * HW + rx];
                        else if (j == 1) val = hmf_b[ry * HW + rx];
                        else             val = 1.0f;
                    }
                }
                v[u] = val;
            }
            uint32_t lp, hp = pack_hl(v[0], v[1], lp);
            *(uint32_t*)(smc + SM_EAH + px * EA_STRIDE + sp * 4) = hp;
            *(uint32_t*)(smc + SM_EAL + px * EA_STRIDE + sp * 4) = lp;
        }
    }
    __syncthreads();
    {
        uint32_t a0 = sb + SM_EAH + (px0 + row_add) * EA_STRIDE + a_half;
        #pragma unroll
        for (int kc = 0; kc < 2; kc++) {
            uint32_t Ah[2][4], Al[2][4];
            #pragma unroll
            for (int mt = 0; mt < 2; mt++) {
                uint32_t aH = a0 + mt * (16 * EA_STRIDE) + kc * 32;
                ldsm_x4(aH, Ah[mt][0], Ah[mt][1], Ah[mt][2], Ah[mt][3]);
                ldsm_x4(aH + (SM_EAL - SM_EAH), Al[mt][0], Al[mt][1], Al[mt][2], Al[mt][3]);
            }
            #pragma unroll
            for (int nbp = 0; nbp < 2; nbp++) {
                uint4 bh = ef4[ebase + nbp * 128 + kc * 64];
                uint4 bl = ef4[ebase + nbp * 128 + kc * 64 + 32];
                #pragma unroll
                for (int mt = 0; mt < 2; mt++) {
                    mma_bf16(acc[1][mt][2 * nbp],     Ah[mt], bh.x, bh.y);
                    mma_bf16(acc[1][mt][2 * nbp + 1], Ah[mt], bh.z, bh.w);
                    mma_bf16(acc[1][mt][2 * nbp],     Ah[mt], bl.x, bl.y);
                    mma_bf16(acc[1][mt][2 * nbp + 1], Ah[mt], bl.z, bl.w);
                    mma_bf16(acc[1][mt][2 * nbp],     Al[mt], bh.x, bh.y);
                    mma_bf16(acc[1][mt][2 * nbp + 1], Al[mt], bh.z, bh.w);
                }
            }
        }
    }

    // ---- epilogues: both rows ----
    #pragma unroll
    for (int rw = 0; rw < 2; rw++) {
        int y = y0 + rw;
        #pragma unroll
        for (int mt = 0; mt < 2; mt++) {
            int r0 = px0 + mt * 16 + (lane >> 2);
            #pragma unroll
            for (int nt = 0; nt < 4; nt++) {
                int oc = h * 32 + nt * 8 + (lane & 3) * 2;
                float bv0 = comp_b[oc], bv1 = comp_b[oc + 1];
                float* o0 = out + (((size_t)b * 64 + oc) * HW + y) * HW;
                float* o1 = o0 + (size_t)HW * HW;
                o0[r0]     = acc[rw][mt][nt][0] + bv0;
                o1[r0]     = acc[rw][mt][nt][1] + bv1;
                o0[r0 + 8] = acc[rw][mt][nt][2] + bv0;
                o1[r0 + 8] = acc[rw][mt][nt][3] + bv1;
            }
        }
    }
}

// ---------------- launch ----------------
extern "C" void kernel_launch(void* const* d_in, const int* in_sizes, int n_in,
                              void* d_out, int out_size) {
    const float* lidar  = (const float*)d_in[0];
    const void*  rcoors = d_in[2];
    const float* rcs    = (const float*)d_in[4];
    const float* gamma  = (const float*)d_in[5];
    const float* att_w  = (const float*)d_in[6];
    const float* att_b  = (const float*)d_in[7];
    const float* comp_w = (const float*)d_in[8];
    const float* comp_b = (const float*)d_in[9];
    float* out = (float*)d_out;

    int B = in_sizes[0] / (C_MID * HW * HW);
    if (B < 1) B = 1; if (B > MAXB) B = MAXB;
    int N = in_sizes[4];

    // k1: detect + fold_a
    detect_fold_a_kernel<<<3, 256>>>((const int*)rcoors, comp_w, att_w, att_b);

    // k2: init heatmaps + fold_b
    int nz = B * HW * HW;
    int init_blocks = (nz + 255) / 256;
    init_fold_b_kernel<<<init_blocks + 38, 256>>>(comp_w, nz, init_blocks);

    // k3: draw
    draw_kernel<<<(N + 7) / 8, 256>>>(rcoors, rcs, gamma, N);

    // k4: conv (2 rows per CTA)
    cudaFuncSetAttribute(conv_mma_kernel,
                         cudaFuncAttributeMaxDynamicSharedMemorySize, SMEM_TOTAL);
    dim3 grid(HW / 2, B);
    conv_mma_kernel<<<grid, NTHREADS, SMEM_TOTAL>>>(lidar, comp_b, out);
}